// round 8
// baseline (speedup 1.0000x reference)
#include <cuda_runtime.h>
#include <math.h>
#include <stdint.h>

// ---------------------------------------------------------------------------
// GraphTrajectoryEncoder: B=4, S=1024, D=512, DEPTH=6, H=8, HD=64, F=2048
// Round 8: pre-truncated tf32 operands (no cvt in hot loops, bit-identical),
// BK=32 3-stage 1-sync GEMMs, leaner flash (split cp.async groups, 4 syncs).
// ---------------------------------------------------------------------------

namespace {
constexpr int Bc = 4, Sc = 1024, Dc = 512, Hc = 8, HDc = 64, Fc = 2048;
constexpr int INNERc = 512;
constexpr int QKVC = 3 * INNERc;   // 1536
constexpr int Mr = Bc * Sc;        // 4096

// flash smem (floats): Qs 8192 | Ks 2x8192 | Vs 8192 | Ps 16384 | redM 512 | redS 512
constexpr int FLASH_SMEM_FLOATS = 50176;
constexpr int FLASH_SMEM_BYTES = FLASH_SMEM_FLOATS * 4;   // 200704

// gemm smem: As 3 x 128*36 | Bs 3 x 32*136
constexpr int GEMM_AS = 128 * 36;          // 4608
constexpr int GEMM_BS = 32 * 136;          // 4352
constexpr int GEMM_SMEM_BYTES = (3 * GEMM_AS + 3 * GEMM_BS) * 4;  // 107520

// truncated-weight scratch offsets (floats)
constexpr size_t SZ_QKV_L = (size_t)Dc * QKVC;     // 786432
constexpr size_t SZ_WOUT_L = (size_t)INNERc * Dc;  // 262144
constexpr size_t SZ_W1_L = (size_t)Dc * Fc;        // 1048576
constexpr size_t SZ_W2_L = (size_t)Fc * Dc;        // 1048576
constexpr size_t OFF_QKV = 0;
constexpr size_t OFF_WOUT = OFF_QKV + 6 * SZ_QKV_L;    // 4718592
constexpr size_t OFF_W1 = OFF_WOUT + 6 * SZ_WOUT_L;    // 6291456
constexpr size_t OFF_W2 = OFF_W1 + 6 * SZ_W1_L;        // 12582912
constexpr size_t WT_TOTAL = OFF_W2 + 6 * SZ_W2_L;      // 18874368
}

// Scratch (allocation-free: module globals)
__device__ __align__(128) float g_n[Mr * Dc];
__device__ __align__(128) float g_qkv[Mr * QKVC];
__device__ __align__(128) float g_o[Mr * INNERc];
__device__ __align__(128) float g_ff[Mr * Fc];
__device__ __align__(128) float g_h[Mr * Dc];
__device__ __align__(128) float g_wt[WT_TOTAL];                     // 75.5 MB
__device__ __align__(128) uint32_t g_pmask[(size_t)Bc * Sc * (Sc / 32)];

// ---------------------------------------------------------------------------
// helpers
// ---------------------------------------------------------------------------
__device__ __forceinline__ uint32_t f2tf(float f) {
    uint32_t u;
    asm("cvt.rna.tf32.f32 %0, %1;" : "=r"(u) : "f"(f));
    return u;
}
__device__ __forceinline__ float trunc_tf(float f) { return __uint_as_float(f2tf(f)); }

__device__ __forceinline__ void mma_tf32(float c[4], uint32_t a0, uint32_t a1,
                                         uint32_t a2, uint32_t a3,
                                         uint32_t b0, uint32_t b1) {
    asm volatile(
        "mma.sync.aligned.m16n8k8.row.col.f32.tf32.tf32.f32 "
        "{%0,%1,%2,%3}, {%4,%5,%6,%7}, {%8,%9}, {%0,%1,%2,%3};\n"
        : "+f"(c[0]), "+f"(c[1]), "+f"(c[2]), "+f"(c[3])
        : "r"(a0), "r"(a1), "r"(a2), "r"(a3), "r"(b0), "r"(b1));
}

__device__ __forceinline__ void cp16(void* smem, const void* gmem) {
    uint32_t s = (uint32_t)__cvta_generic_to_shared(smem);
    asm volatile("cp.async.cg.shared.global [%0], [%1], 16;" :: "r"(s), "l"(gmem));
}
#define CP_COMMIT() asm volatile("cp.async.commit_group;")
#define CP_WAIT2()  asm volatile("cp.async.wait_group 2;")
#define CP_WAIT1()  asm volatile("cp.async.wait_group 1;")

// ---------------------------------------------------------------------------
// Block-wide reduction for 256 threads
// ---------------------------------------------------------------------------
template <bool MAXOP>
__device__ __forceinline__ float block_reduce256(float v) {
    __shared__ float red[8];
    const int t = threadIdx.x;
#pragma unroll
    for (int o = 16; o > 0; o >>= 1) {
        float u = __shfl_down_sync(0xffffffffu, v, o);
        v = MAXOP ? fmaxf(v, u) : v + u;
    }
    if ((t & 31) == 0) red[t >> 5] = v;
    __syncthreads();
    if (t < 32) {
        v = (t < 8) ? red[t] : (MAXOP ? -INFINITY : 0.0f);
#pragma unroll
        for (int o = 4; o > 0; o >>= 1) {
            float u = __shfl_down_sync(0xffffffffu, v, o);
            v = MAXOP ? fmaxf(v, u) : v + u;
        }
        if (t == 0) red[0] = v;
    }
    __syncthreads();
    float r = red[0];
    __syncthreads();
    return r;
}

// ---------------------------------------------------------------------------
// Weight truncation (fp32 -> tf32-rounded fp32), once per launch
// ---------------------------------------------------------------------------
__global__ void trunc_kernel(const float* __restrict__ s, float* __restrict__ d, int n4) {
    const int i = blockIdx.x * 256 + threadIdx.x;
    if (i >= n4) return;
    float4 v = reinterpret_cast<const float4*>(s)[i];
    v.x = trunc_tf(v.x); v.y = trunc_tf(v.y);
    v.z = trunc_tf(v.z); v.w = trunc_tf(v.w);
    reinterpret_cast<float4*>(d)[i] = v;
}

// ---------------------------------------------------------------------------
// LayerNorm over D=512, one block (256 threads) per row; tf32-truncated out.
// ---------------------------------------------------------------------------
__global__ void ln_kernel(const float* __restrict__ h, const float* __restrict__ w,
                          const float* __restrict__ b, float* __restrict__ out) {
    const int row = blockIdx.x;
    const int t = threadIdx.x;
    const float2 v = *reinterpret_cast<const float2*>(h + (size_t)row * Dc + t * 2);
    const float mean = block_reduce256<false>(v.x + v.y) * (1.0f / Dc);
    const float d0 = v.x - mean, d1 = v.y - mean;
    const float var = block_reduce256<false>(d0 * d0 + d1 * d1) * (1.0f / Dc);
    const float rstd = rsqrtf(var + 1e-5f);
    const float2 ww = *reinterpret_cast<const float2*>(w + t * 2);
    const float2 bb = *reinterpret_cast<const float2*>(b + t * 2);
    float2 o2 = make_float2(trunc_tf(d0 * rstd * ww.x + bb.x),
                            trunc_tf(d1 * rstd * ww.y + bb.y));
    *reinterpret_cast<float2*>(out + (size_t)row * Dc + t * 2) = o2;
}

// ---------------------------------------------------------------------------
// Pack graph mask to bits (OR self-loop), once per launch.
// ---------------------------------------------------------------------------
__global__ void pack_mask_kernel(const int* __restrict__ gmask,
                                 uint32_t* __restrict__ pm) {
    const size_t idx = (size_t)blockIdx.x * 256 + threadIdx.x;  // over B*S*S
    const int c = (int)(idx & (Sc - 1));
    const int r = (int)((idx >> 10) & (Sc - 1));
    const bool keep = (gmask[idx] > 0) || (c == r);
    const uint32_t w = __ballot_sync(0xffffffffu, keep);
    if ((threadIdx.x & 31) == 0) pm[idx >> 5] = w;
}

// ---------------------------------------------------------------------------
// tf32 MMA GEMM: C = A@B (+bias)(gelu)(+res)(trunc). A,B pre-truncated.
// 128x128 tile, BK=32, 3-stage cp.async, ONE sync per k-tile.
// As [m][k] stride 36 (bank (4g+t)%32 distinct); Bs [k][n] stride 136.
// ---------------------------------------------------------------------------
__global__ void __launch_bounds__(256, 2) gemm_tf32_kernel(
    const float* __restrict__ A, const float* __restrict__ B, float* __restrict__ C,
    int M, int N, int K, int lda, int ldb, int ldc,
    const float* __restrict__ bias, const float* __restrict__ res,
    int gelu, int trunc) {
    extern __shared__ float gsm[];
    float* As = gsm;                    // 3 x 4608
    float* Bs = gsm + 3 * GEMM_AS;      // 3 x 4352
    const int tid = threadIdx.x;
    const int row0 = blockIdx.y * 128, col0 = blockIdx.x * 128;
    const int lane = tid & 31, wid = tid >> 5;
    const int g = lane >> 2, t = lane & 3;
    const int wm = (wid & 1) * 64, wn = (wid >> 1) * 32;
    const int ar = tid >> 1, ac = (tid & 1) * 16;
    const int br = tid >> 3, bc = (tid & 7) * 16;
    const float* Asrc = A + (size_t)(row0 + ar) * lda + ac;
    const float* Bsrc = B + (size_t)br * ldb + col0 + bc;
    const int ntiles = K >> 5;

    auto loadT = [&](int s, int k0) {
        float* da = As + s * GEMM_AS + ar * 36 + ac;
        const float* sa = Asrc + k0;
        cp16(da, sa); cp16(da + 4, sa + 4); cp16(da + 8, sa + 8); cp16(da + 12, sa + 12);
        float* db = Bs + s * GEMM_BS + br * 136 + bc;
        const float* sb = Bsrc + (size_t)k0 * ldb;
        cp16(db, sb); cp16(db + 4, sb + 4); cp16(db + 8, sb + 8); cp16(db + 12, sb + 12);
    };

    loadT(0, 0);  CP_COMMIT();
    loadT(1, 32); CP_COMMIT();

    float acc[4][4][4] = {};
    for (int it = 0; it < ntiles; it++) {
        CP_WAIT1();
        __syncthreads();
        const float* Sa = As + (it % 3) * GEMM_AS;
        const float* Sb = Bs + (it % 3) * GEMM_BS;
#pragma unroll
        for (int ks = 0; ks < 32; ks += 8) {
            uint32_t af[4][4], bf[4][2];
#pragma unroll
            for (int mi = 0; mi < 4; mi++) {
                const float* ap = Sa + (wm + mi * 16 + g) * 36 + ks;
                af[mi][0] = __float_as_uint(ap[t]);
                af[mi][1] = __float_as_uint(ap[288 + t]);       // +8 rows * 36
                af[mi][2] = __float_as_uint(ap[t + 4]);
                af[mi][3] = __float_as_uint(ap[288 + t + 4]);
            }
#pragma unroll
            for (int ni = 0; ni < 4; ni++) {
                const float* bp = Sb + (ks + t) * 136 + wn + ni * 8 + g;
                bf[ni][0] = __float_as_uint(bp[0]);
                bf[ni][1] = __float_as_uint(bp[4 * 136]);
            }
#pragma unroll
            for (int mi = 0; mi < 4; mi++)
#pragma unroll
                for (int ni = 0; ni < 4; ni++)
                    mma_tf32(acc[mi][ni], af[mi][0], af[mi][1], af[mi][2], af[mi][3],
                             bf[ni][0], bf[ni][1]);
        }
        if (it + 2 < ntiles) loadT((it + 2) % 3, (it + 2) * 32);
        CP_COMMIT();
    }

#pragma unroll
    for (int mi = 0; mi < 4; mi++) {
#pragma unroll
        for (int ni = 0; ni < 4; ni++) {
            const int cc = col0 + wn + ni * 8 + t * 2;
            float bx = 0.f, by = 0.f;
            if (bias) { bx = __ldg(&bias[cc]); by = __ldg(&bias[cc + 1]); }
#pragma unroll
            for (int half = 0; half < 2; half++) {
                const int r = row0 + wm + mi * 16 + g + half * 8;
                float v0 = acc[mi][ni][half * 2 + 0] + bx;
                float v1 = acc[mi][ni][half * 2 + 1] + by;
                if (gelu) {
                    v0 = 0.5f * v0 * (1.0f + erff(v0 * 0.7071067811865475f));
                    v1 = 0.5f * v1 * (1.0f + erff(v1 * 0.7071067811865475f));
                }
                if (res) {
                    const float2 rr = *reinterpret_cast<const float2*>(res + (size_t)r * ldc + cc);
                    v0 += rr.x; v1 += rr.y;
                }
                if (trunc) { v0 = trunc_tf(v0); v1 = trunc_tf(v1); }
                *reinterpret_cast<float2*>(C + (size_t)r * ldc + cc) = make_float2(v0, v1);
            }
        }
    }
}

// ---------------------------------------------------------------------------
// Flash attention (Q/K/V pre-truncated tf32 -> no cvt in mma paths).
// Per (q-tile 128, b, h): loop 8 k-tiles: S = mask(QK^T/8), online softmax,
// O += P V.  256 threads, warps 2(M)x4(N). 4 syncthreads per iteration.
// cp.async groups: V committed before K-prefetch so WAIT1 frees V only.
// ---------------------------------------------------------------------------
__global__ void __launch_bounds__(256, 1) flash_attn_kernel(
    const float* __restrict__ qkv, const uint32_t* __restrict__ pmask,
    float* __restrict__ o) {
    extern __shared__ float sm[];
    float* Qs = sm;                 // [128][64]
    float* KsB = sm + 8192;         // 2 x [128][64]
    float* Vs = sm + 24576;         // [128][64]
    float* Ps = sm + 32768;         // [128][128]
    float* redM = sm + 49152;       // [4][128]
    float* redS = sm + 49664;       // [4][128]

    const int tid = threadIdx.x;
    const int row0 = blockIdx.x * 128;
    const int bh = blockIdx.y, b = bh >> 3, hh = bh & 7;
    const int lane = tid & 31, wid = tid >> 5;
    const int g = lane >> 2, t = lane & 3;
    const int wm = (wid & 1) * 64;
    const int wn = (wid >> 1) * 32;
    const int wno = (wid >> 1) * 16;
    const int nw = wid >> 1;

    const float* Qg = qkv + (size_t)(b * Sc + row0) * QKVC + hh * HDc;
    const float* Kg = qkv + (size_t)b * Sc * QKVC + INNERc + hh * HDc;
    const float* Vg = qkv + (size_t)b * Sc * QKVC + 2 * INNERc + hh * HDc;

    const int lr = tid >> 1;
    const int lcb = (tid & 1) * 32;
    const int swA = (lr & 7) << 2;
    const int swV = (lr & 3) << 3;

    // prologue: Q + K0  (group 0)
    {
        const float* qsrc = Qg + (size_t)lr * QKVC + lcb;
        float* qdst = Qs + lr * 64;
        const float* ksrc = Kg + (size_t)lr * QKVC + lcb;
        float* kdst = KsB + lr * 64;
#pragma unroll
        for (int j = 0; j < 8; j++) {
            cp16(qdst + ((lcb + 4 * j) ^ swA), qsrc + 4 * j);
            cp16(kdst + ((lcb + 4 * j) ^ swA), ksrc + 4 * j);
        }
        CP_COMMIT();
    }

    float oacc[4][2][4] = {};
    float mrun[4][2], lrun[4][2];
#pragma unroll
    for (int mi = 0; mi < 4; mi++) {
        mrun[mi][0] = -INFINITY; mrun[mi][1] = -INFINITY;
        lrun[mi][0] = 0.0f; lrun[mi][1] = 0.0f;
    }

    for (int kt = 0; kt < 8; kt++) {
        // V tile kt (own group, committed FIRST)
        {
            const float* vsrc = Vg + (size_t)(kt * 128 + lr) * QKVC + lcb;
            float* vdst = Vs + lr * 64;
#pragma unroll
            for (int j = 0; j < 8; j++) cp16(vdst + ((lcb + 4 * j) ^ swV), vsrc + 4 * j);
        }
        CP_COMMIT();
        // K tile kt+1 prefetch (own group, committed LAST -> may stay in flight)
        if (kt + 1 < 8) {
            const float* ksrc = Kg + (size_t)((kt + 1) * 128 + lr) * QKVC + lcb;
            float* kdst = KsB + ((kt + 1) & 1) * 8192 + lr * 64;
#pragma unroll
            for (int j = 0; j < 8; j++) cp16(kdst + ((lcb + 4 * j) ^ swA), ksrc + 4 * j);
        }
        CP_COMMIT();
        CP_WAIT2();
        __syncthreads();   // syncA: Q + K_kt resident

        // ---- S = Q K^T ----
        const float* Kc = KsB + (kt & 1) * 8192;
        float sacc[4][4][4] = {};
#pragma unroll
        for (int ks = 0; ks < 64; ks += 8) {
            uint32_t af[4][4], bf[4][2];
#pragma unroll
            for (int mi = 0; mi < 4; mi++) {
                const float* q0 = Qs + (wm + mi * 16 + g) * 64;
                const float* q1 = q0 + 8 * 64;
                const int c0 = (ks + t) ^ (g << 2), c1 = (ks + t + 4) ^ (g << 2);
                af[mi][0] = __float_as_uint(q0[c0]); af[mi][1] = __float_as_uint(q1[c0]);
                af[mi][2] = __float_as_uint(q0[c1]); af[mi][3] = __float_as_uint(q1[c1]);
            }
#pragma unroll
            for (int ni = 0; ni < 4; ni++) {
                const float* kp = Kc + (wn + ni * 8 + g) * 64;
                bf[ni][0] = __float_as_uint(kp[(ks + t) ^ (g << 2)]);
                bf[ni][1] = __float_as_uint(kp[(ks + t + 4) ^ (g << 2)]);
            }
#pragma unroll
            for (int mi = 0; mi < 4; mi++)
#pragma unroll
                for (int ni = 0; ni < 4; ni++)
                    mma_tf32(sacc[mi][ni], af[mi][0], af[mi][1], af[mi][2], af[mi][3],
                             bf[ni][0], bf[ni][1]);
        }

        // ---- mask + scale + per-warp row max -> redM ----
        uint32_t mword[4][2];
#pragma unroll
        for (int mi = 0; mi < 4; mi++)
#pragma unroll
            for (int hf = 0; hf < 2; hf++) {
                const int row = row0 + wm + mi * 16 + g + 8 * hf;
                mword[mi][hf] = __ldg(&pmask[((size_t)b * Sc + row) * 32 + kt * 4 + (wn >> 5)]);
            }
#pragma unroll
        for (int mi = 0; mi < 4; mi++)
#pragma unroll
            for (int hf = 0; hf < 2; hf++) {
                float rmax = -INFINITY;
#pragma unroll
                for (int ni = 0; ni < 4; ni++)
#pragma unroll
                    for (int jj = 0; jj < 2; jj++) {
                        float v = sacc[mi][ni][hf * 2 + jj];
                        const bool keep = (mword[mi][hf] >> (ni * 8 + 2 * t + jj)) & 1u;
                        v = keep ? v * 0.125f : -1e9f;
                        sacc[mi][ni][hf * 2 + jj] = v;
                        rmax = fmaxf(rmax, v);
                    }
                rmax = fmaxf(rmax, __shfl_xor_sync(0xffffffffu, rmax, 1));
                rmax = fmaxf(rmax, __shfl_xor_sync(0xffffffffu, rmax, 2));
                if (t == 0) redM[nw * 128 + wm + mi * 16 + g + 8 * hf] = rmax;
            }
        __syncthreads();   // sync1: warp maxes visible

        // ---- combine maxes, exp, partial sums -> redS; stage P (tf32) ----
        float cf[4][2];
#pragma unroll
        for (int mi = 0; mi < 4; mi++)
#pragma unroll
            for (int hf = 0; hf < 2; hf++) {
                const int row = wm + mi * 16 + g + 8 * hf;
                const float mt = fmaxf(fmaxf(redM[row], redM[128 + row]),
                                       fmaxf(redM[256 + row], redM[384 + row]));
                const float mo = mrun[mi][hf];
                const float mn = fmaxf(mo, mt);
                cf[mi][hf] = __expf(mo - mn);
                mrun[mi][hf] = mn;
                float s = 0.0f;
#pragma unroll
                for (int ni = 0; ni < 4; ni++)
#pragma unroll
                    for (int jj = 0; jj < 2; jj++) {
                        const float p = __expf(sacc[mi][ni][hf * 2 + jj] - mn);
                        sacc[mi][ni][hf * 2 + jj] = p;
                        s += p;
                    }
                s += __shfl_xor_sync(0xffffffffu, s, 1);
                s += __shfl_xor_sync(0xffffffffu, s, 2);
                if (t == 0) redS[nw * 128 + row] = s;
            }
#pragma unroll
        for (int mi = 0; mi < 4; mi++)
#pragma unroll
            for (int ni = 0; ni < 4; ni++)
#pragma unroll
                for (int hf = 0; hf < 2; hf++) {
                    const int row = wm + mi * 16 + g + 8 * hf;
                    const int c = (wn + ni * 8 + 2 * t) ^ (g << 2);
                    *reinterpret_cast<float2*>(&Ps[row * 128 + c]) =
                        make_float2(trunc_tf(sacc[mi][ni][hf * 2]),
                                    trunc_tf(sacc[mi][ni][hf * 2 + 1]));
                }
#pragma unroll
        for (int mi = 0; mi < 4; mi++) {
            lrun[mi][0] *= cf[mi][0];
            lrun[mi][1] *= cf[mi][1];
#pragma unroll
            for (int ni = 0; ni < 2; ni++)
#pragma unroll
                for (int j = 0; j < 4; j++)
                    oacc[mi][ni][j] *= cf[mi][j >> 1];
        }
        CP_WAIT1();        // V_kt done (K_{kt+1} group may remain in flight)
        __syncthreads();   // sync2: V, Ps, redS visible

#pragma unroll
        for (int mi = 0; mi < 4; mi++)
#pragma unroll
            for (int hf = 0; hf < 2; hf++) {
                const int row = wm + mi * 16 + g + 8 * hf;
                lrun[mi][hf] += redS[row] + redS[128 + row] + redS[256 + row] + redS[384 + row];
            }

        // ---- O += P V ----
#pragma unroll 4
        for (int ks = 0; ks < 128; ks += 8) {
            uint32_t af[4][4], bf[2][2];
#pragma unroll
            for (int mi = 0; mi < 4; mi++) {
                const float* p0 = Ps + (wm + mi * 16 + g) * 128;
                const float* p1 = p0 + 8 * 128;
                const int c0 = (ks + t) ^ (g << 2), c1 = (ks + t + 4) ^ (g << 2);
                af[mi][0] = __float_as_uint(p0[c0]); af[mi][1] = __float_as_uint(p1[c0]);
                af[mi][2] = __float_as_uint(p0[c1]); af[mi][3] = __float_as_uint(p1[c1]);
            }
#pragma unroll
            for (int ni = 0; ni < 2; ni++) {
                const int n = wno + ni * 8 + g;
                bf[ni][0] = __float_as_uint(Vs[(ks + t) * 64 + (n ^ (t << 3))]);
                bf[ni][1] = __float_as_uint(Vs[(ks + t + 4) * 64 + (n ^ (t << 3))]);
            }
#pragma unroll
            for (int mi = 0; mi < 4; mi++)
#pragma unroll
                for (int ni = 0; ni < 2; ni++)
                    mma_tf32(oacc[mi][ni], af[mi][0], af[mi][1], af[mi][2], af[mi][3],
                             bf[ni][0], bf[ni][1]);
        }
        __syncthreads();   // syncEnd: Ps/Vs reusable
    }

    // ---- epilogue: O /= l, tf32-truncate (o feeds Wout gemm), write ----
#pragma unroll
    for (int mi = 0; mi < 4; mi++)
#pragma unroll
        for (int ni = 0; ni < 2; ni++)
#pragma unroll
            for (int hf = 0; hf < 2; hf++) {
                const int row = row0 + wm + mi * 16 + g + 8 * hf;
                const int c = hh * HDc + wno + ni * 8 + 2 * t;
                const float il = 1.0f / lrun[mi][hf];
                *reinterpret_cast<float2*>(&o[(size_t)(b * Sc + row) * INNERc + c]) =
                    make_float2(trunc_tf(oacc[mi][ni][hf * 2] * il),
                                trunc_tf(oacc[mi][ni][hf * 2 + 1] * il));
            }
}

// ---------------------------------------------------------------------------
// Host launcher
// ---------------------------------------------------------------------------
extern "C" void kernel_launch(void* const* d_in, const int* in_sizes, int n_in,
                              void* d_out, int out_size) {
    (void)in_sizes; (void)n_in; (void)out_size;
    const float* x     = (const float*)d_in[0];
    const int*   gmask = (const int*)d_in[1];
    const float* ln1w = (const float*)d_in[2];
    const float* ln1b = (const float*)d_in[3];
    const float* Wqkv = (const float*)d_in[4];
    const float* Wout = (const float*)d_in[5];
    const float* bout = (const float*)d_in[6];
    const float* ln2w = (const float*)d_in[7];
    const float* ln2b = (const float*)d_in[8];
    const float* W1   = (const float*)d_in[9];
    const float* b1   = (const float*)d_in[10];
    const float* W2   = (const float*)d_in[11];
    const float* b2   = (const float*)d_in[12];
    float* out = (float*)d_out;

    float *pn, *pqkv, *po, *pff, *ph, *pwt;
    uint32_t* ppm;
    cudaGetSymbolAddress((void**)&pn, g_n);
    cudaGetSymbolAddress((void**)&pqkv, g_qkv);
    cudaGetSymbolAddress((void**)&po, g_o);
    cudaGetSymbolAddress((void**)&pff, g_ff);
    cudaGetSymbolAddress((void**)&ph, g_h);
    cudaGetSymbolAddress((void**)&pwt, g_wt);
    cudaGetSymbolAddress((void**)&ppm, g_pmask);

    cudaFuncSetAttribute(flash_attn_kernel,
                         cudaFuncAttributeMaxDynamicSharedMemorySize, FLASH_SMEM_BYTES);
    cudaFuncSetAttribute(gemm_tf32_kernel,
                         cudaFuncAttributeMaxDynamicSharedMemorySize, GEMM_SMEM_BYTES);

    pack_mask_kernel<<<(Bc * Sc * Sc) / 256, 256>>>(gmask, ppm);
    trunc_kernel<<<(int)((6 * SZ_QKV_L / 4 + 255) / 256), 256>>>(Wqkv, pwt + OFF_QKV, (int)(6 * SZ_QKV_L / 4));
    trunc_kernel<<<(int)((6 * SZ_WOUT_L / 4 + 255) / 256), 256>>>(Wout, pwt + OFF_WOUT, (int)(6 * SZ_WOUT_L / 4));
    trunc_kernel<<<(int)((6 * SZ_W1_L / 4 + 255) / 256), 256>>>(W1, pwt + OFF_W1, (int)(6 * SZ_W1_L / 4));
    trunc_kernel<<<(int)((6 * SZ_W2_L / 4 + 255) / 256), 256>>>(W2, pwt + OFF_W2, (int)(6 * SZ_W2_L / 4));

    for (int l = 0; l < 6; l++) {
        const float* hin = (l == 0) ? x : ph;

        // --- attention block ---
        ln_kernel<<<Mr, 256>>>(hin, ln1w + l * Dc, ln1b + l * Dc, pn);
        gemm_tf32_kernel<<<dim3(QKVC / 128, Mr / 128), 256, GEMM_SMEM_BYTES>>>(
            pn, pwt + OFF_QKV + l * SZ_QKV_L, pqkv,
            Mr, QKVC, Dc, Dc, QKVC, QKVC, nullptr, nullptr, 0, 1);
        flash_attn_kernel<<<dim3(Sc / 128, Bc * Hc), 256, FLASH_SMEM_BYTES>>>(
            pqkv, ppm, po);
        gemm_tf32_kernel<<<dim3(Dc / 128, Mr / 128), 256, GEMM_SMEM_BYTES>>>(
            po, pwt + OFF_WOUT + l * SZ_WOUT_L, ph,
            Mr, Dc, INNERc, INNERc, Dc, Dc, bout + l * Dc, hin, 0, 0);

        // --- feedforward block ---
        ln_kernel<<<Mr, 256>>>(ph, ln2w + l * Dc, ln2b + l * Dc, pn);
        gemm_tf32_kernel<<<dim3(Fc / 128, Mr / 128), 256, GEMM_SMEM_BYTES>>>(
            pn, pwt + OFF_W1 + l * SZ_W1_L, pff,
            Mr, Fc, Dc, Dc, Fc, Fc, b1 + l * Fc, nullptr, 1, 1);
        float* cdst = (l == 5) ? out : ph;
        gemm_tf32_kernel<<<dim3(Dc / 128, Mr / 128), 256, GEMM_SMEM_BYTES>>>(
            pff, pwt + OFF_W2 + l * SZ_W2_L, cdst,
            Mr, Dc, Fc, Fc, Dc, Dc, b2 + l * Dc, ph, 0, 0);
    }
}